// round 1
// baseline (speedup 1.0000x reference)
#include <cuda_runtime.h>
#include <cstdint>
#include <cstddef>

#define NN 1024
#define BB 32

// ---------------- device scratch (no allocations allowed) ----------------
static __device__ float2   g_tw[NN];        // W1024^{lane*brev5(j)} table
static __device__ float2   g_pa[BB * NN];   // analytic signal
static __device__ float2   g_bb[BB * NN];   // pa * SHIFT_FACTOR
static __device__ double   g_Sp[BB];        // sum of unnormalized shg
static __device__ double   g_Spt[BB];       // sum shg * tref
static __device__ double   g_St[BB];        // sum tref
static __device__ double   g_Stt[BB];       // sum tref^2
static __device__ unsigned g_M[BB];         // max shg (float bits)

__device__ __forceinline__ int br5(int j) {
    return (int)(__brev((unsigned)j) >> 27);
}

// ---------------- fully unrolled radix-2 DIF FFT-32 in registers ----------
// input natural order, output bit-reversed: out[j] = X[brev5(j)]
__device__ __forceinline__ void fft32(float* ar, float* ai) {
    const float W32r[16] = {
        1.00000000f, 0.98078528f, 0.92387953f, 0.83146961f,
        0.70710678f, 0.55557023f, 0.38268343f, 0.19509032f,
        0.00000000f,-0.19509032f,-0.38268343f,-0.55557023f,
       -0.70710678f,-0.83146961f,-0.92387953f,-0.98078528f };
    const float W32i[16] = {
        0.00000000f,-0.19509032f,-0.38268343f,-0.55557023f,
       -0.70710678f,-0.83146961f,-0.92387953f,-0.98078528f,
       -1.00000000f,-0.98078528f,-0.92387953f,-0.83146961f,
       -0.70710678f,-0.55557023f,-0.38268343f,-0.19509032f };
    #pragma unroll
    for (int st = 0; st < 5; st++) {
        const int h = 16 >> st;
        const int tstep = 1 << st;
        #pragma unroll
        for (int s = 0; s < 32; s += 2 * h) {
            #pragma unroll
            for (int j = 0; j < h; j++) {
                const int i0 = s + j, i1 = i0 + h;
                float ur = ar[i0], ui = ai[i0];
                float vr = ar[i1], vi = ai[i1];
                ar[i0] = ur + vr; ai[i0] = ui + vi;
                float dr = ur - vr, di = ui - vi;
                const int w = j * tstep;
                if (w == 0)      { ar[i1] = dr;  ai[i1] = di;  }
                else if (w == 8) { ar[i1] = di;  ai[i1] = -dr; }   // *(0,-1)
                else {
                    float wr = W32r[w], wi = W32i[w];
                    ar[i1] = dr * wr - di * wi;
                    ai[i1] = di * wr + dr * wi;
                }
            }
        }
    }
}

// FFT-1024: lane t holds x[t + 32*q] in reg q. Output: reg j of lane l holds
// X[l + 32*brev5(j)].
__device__ __forceinline__ void fft1024(float* xr, float* xi,
                                        float* sre, float* sim, int lane) {
    fft32(xr, xi);                 // per-lane DFT over q
    #pragma unroll
    for (int j = 0; j < 32; j++) { // twiddle W1024^{lane * brev5(j)}
        float2 w = g_tw[j * 32 + lane];
        float r = xr[j] * w.x - xi[j] * w.y;
        xi[j]   = xi[j] * w.x + xr[j] * w.y;
        xr[j]   = r;
    }
    __syncwarp();
    #pragma unroll
    for (int j = 0; j < 32; j++) { // transpose (un-bit-reversing k1)
        int k1 = br5(j);
        sre[k1 * 33 + lane] = xr[j];
        sim[k1 * 33 + lane] = xi[j];
    }
    __syncwarp();
    #pragma unroll
    for (int r = 0; r < 32; r++) {
        xr[r] = sre[lane * 33 + r];
        xi[r] = sim[lane * 33 + r];
    }
    __syncwarp();
    fft32(xr, xi);                 // DFT over former lane index
}

// ---------------- K0: twiddle table + accumulator reset -------------------
__global__ void k_init() {
    int tid = threadIdx.x;
    int j = tid >> 5, t = tid & 31;
    int e = (t * br5(j)) & 1023;
    double s, c;
    sincospi(-(double)e / 512.0, &s, &c);
    g_tw[tid] = make_float2((float)c, (float)s);
    if (tid < BB) {
        g_Sp[tid] = 0.0; g_Spt[tid] = 0.0;
        g_St[tid] = 0.0; g_Stt[tid] = 0.0;
        g_M[tid] = 0u;
    }
}

// ---------------- K1: Hilbert (analytic signal) + SHIFT_FACTOR fold -------
__global__ void __launch_bounds__(128) k_hilbert(const float* __restrict__ pred) {
    __shared__ float sre[4][33 * 32];
    __shared__ float sim[4][33 * 32];
    int warp = threadIdx.x >> 5, lane = threadIdx.x & 31;
    int b = blockIdx.x * 4 + warp;

    float xr[32], xi[32];
    const float* p = pred + b * NN;
    #pragma unroll
    for (int q = 0; q < 32; q++) { xr[q] = p[lane + 32 * q]; xi[q] = 0.f; }

    fft1024(xr, xi, sre[warp], sim[warp], lane);

    // mask (0 for k<512, 1 at 512, 2 for k>512), conj, rearrange to "time" layout
    float yr[32], yi[32];
    #pragma unroll
    for (int p2 = 0; p2 < 32; p2++) {
        int j = br5(p2);                 // source reg with freq lane + 32*p2
        int k = lane + 32 * p2;
        float f = (k > 512) ? 2.f : ((k == 512) ? 1.f : 0.f);
        yr[p2] =  xr[j] * f;
        yi[p2] = -xi[j] * f;
    }
    fft1024(yr, yi, sre[warp], sim[warp], lane);  // ifft via conj trick

    const double phi = 2.0 * 1.175e15 * 1.5e-15;  // 2*W_CENTER*DELTA_TAU
    #pragma unroll
    for (int j = 0; j < 32; j++) {
        int m = lane + 32 * br5(j);
        float prr =  yr[j] * (1.f / 1024.f);
        float pii = -yi[j] * (1.f / 1024.f);
        g_pa[b * NN + m] = make_float2(prr, pii);
        float argf = (float)(phi * (double)(m - 512));
        double sd, cd;
        sincos((double)argf, &sd, &cd);
        float cr = (float)cd, si = (float)sd;     // SF = cr - i*si
        g_bb[b * NN + m] = make_float2(prr * cr + pii * si,
                                       pii * cr - prr * si);
    }
}

// ---------------- K2: SHG rows — FFT + streaming reduction ----------------
__global__ void __launch_bounds__(128) k_shg(const float* __restrict__ tref) {
    __shared__ float sre[4][33 * 32];
    __shared__ float sim[4][33 * 32];
    __shared__ float s_acc[4][4];
    __shared__ float s_mx[4];
    int warp = threadIdx.x >> 5, lane = threadIdx.x & 31;
    int w = blockIdx.x * 4 + warp;
    int b = w >> 10;          // 1024 rows per batch; whole CTA shares b
    int d = w & 1023;

    const float2* pb = g_bb + b * NN;
    const float2* pa = g_pa + b * NN;
    float xr[32], xi[32];
    #pragma unroll
    for (int q = 0; q < 32; q++) {
        int n = lane + 32 * q;
        float2 bv = pb[n];
        float2 av = pa[(n - d + 512) & 1023];
        xr[q] = bv.x * av.x - bv.y * av.y;
        xi[q] = bv.x * av.y + bv.y * av.x;
    }

    fft1024(xr, xi, sre[warp], sim[warp], lane);

    const float* trow = tref + (size_t)(b * 1024 + d) * 1024;
    float sp = 0.f, spt = 0.f, st = 0.f, stt = 0.f, mx = 0.f;
    #pragma unroll
    for (int j = 0; j < 32; j++) {
        float m = xr[j] * xr[j] + xi[j] * xi[j];
        int col = (lane + 32 * br5(j) + 512) & 1023;  // output fftshift remap
        float tv = __ldcs(trow + col);
        sp += m; spt += m * tv; st += tv; stt += tv * tv;
        mx = fmaxf(mx, m);
    }
    #pragma unroll
    for (int o = 16; o; o >>= 1) {
        sp  += __shfl_xor_sync(0xffffffffu, sp, o);
        spt += __shfl_xor_sync(0xffffffffu, spt, o);
        st  += __shfl_xor_sync(0xffffffffu, st, o);
        stt += __shfl_xor_sync(0xffffffffu, stt, o);
        mx = fmaxf(mx, __shfl_xor_sync(0xffffffffu, mx, o));
    }
    if (lane == 0) {
        s_acc[warp][0] = sp; s_acc[warp][1] = spt;
        s_acc[warp][2] = st; s_acc[warp][3] = stt;
        s_mx[warp] = mx;
    }
    __syncthreads();
    if (threadIdx.x == 0) {
        double a0 = 0, a1 = 0, a2 = 0, a3 = 0; float mm = 0.f;
        #pragma unroll
        for (int i2 = 0; i2 < 4; i2++) {
            a0 += (double)s_acc[i2][0]; a1 += (double)s_acc[i2][1];
            a2 += (double)s_acc[i2][2]; a3 += (double)s_acc[i2][3];
            mm = fmaxf(mm, s_mx[i2]);
        }
        atomicAdd(&g_Sp[b],  a0);
        atomicAdd(&g_Spt[b], a1);
        atomicAdd(&g_St[b],  a2);
        atomicAdd(&g_Stt[b], a3);
        atomicMax(&g_M[b], __float_as_uint(mm));
    }
}

// ---------------- K3: MSE + FROG + final mean -----------------------------
__global__ void __launch_bounds__(1024) k_final(const float* __restrict__ label,
                                                float* __restrict__ out) {
    __shared__ float s_loss[32];
    int lane = threadIdx.x & 31;
    int b = threadIdx.x >> 5;            // warp b handles batch b
    const float* lab = label + b * 2 * NN;

    // pass 1: first/last indices per component (defaults 0 / N-1)
    int fr = NN, fi = NN, lastr = -1, lasti = -1;
    #pragma unroll
    for (int q = 0; q < 32; q++) {
        int t = lane + 32 * q;
        float lr = lab[t], li = lab[NN + t];
        if (fabsf(lr) > 0.01f) { fr = min(fr, t); lastr = max(lastr, t); }
        if (fabsf(li) > 0.01f) { fi = min(fi, t); lasti = max(lasti, t); }
    }
    #pragma unroll
    for (int o = 16; o; o >>= 1) {
        fr    = min(fr,    __shfl_xor_sync(0xffffffffu, fr, o));
        fi    = min(fi,    __shfl_xor_sync(0xffffffffu, fi, o));
        lastr = max(lastr, __shfl_xor_sync(0xffffffffu, lastr, o));
        lasti = max(lasti, __shfl_xor_sync(0xffffffffu, lasti, o));
    }
    if (fr == NN)  fr = 0;
    if (fi == NN)  fi = 0;
    if (lastr < 0) lastr = NN - 1;
    if (lasti < 0) lasti = NN - 1;
    int first = min(fr, fi), last = max(lastr, lasti);

    // pass 2: masked MSE terms
    float s = 0.f;
    #pragma unroll
    for (int q = 0; q < 32; q++) {
        int t = lane + 32 * q;
        float2 pav = g_pa[b * NN + t];
        float pr = pav.x, pi = pav.y;
        float lr = lab[t], li = lab[NN + t];
        bool inr = (t >= first) && (t < last);
        float pm = inr ? 10.f : 1.f;
        float d1 = pr - lr, d2 = pi - li;
        float d3 = (pr * pr + pi * pi) - (lr * lr + li * li);
        float dph = atan2f(pi, pr) - atan2f(li, lr);
        s += (d1 * d1 + d2 * d2 + d3 * d3) * pm + (inr ? dph * dph : 0.f);
    }
    #pragma unroll
    for (int o = 16; o; o >>= 1) s += __shfl_xor_sync(0xffffffffu, s, o);

    if (lane == 0) {
        float mse = s * (1.f / (4.f * 1024.f));    // /N and /MSE_WSUM
        double M   = (double)__uint_as_float(g_M[b]);
        double mu  = (g_Spt[b] / M) / g_Stt[b];
        double dif = g_Sp[b] / M - mu * g_St[b];
        float frog = (float)(fabs(dif) * (1.0 / 1024.0));  // sqrt(r/N^2)
        s_loss[b] = mse + frog;
    }
    __syncthreads();
    if (threadIdx.x < 32) {
        float v = s_loss[threadIdx.x];
        #pragma unroll
        for (int o = 16; o; o >>= 1) v += __shfl_xor_sync(0xffffffffu, v, o);
        if (threadIdx.x == 0) out[0] = v * (1.f / 32.f);
    }
}

// ---------------- launch ---------------------------------------------------
extern "C" void kernel_launch(void* const* d_in, const int* in_sizes, int n_in,
                              void* d_out, int out_size) {
    (void)in_sizes; (void)n_in; (void)out_size;
    const float* pred  = (const float*)d_in[0];   // (32, 1024)
    const float* label = (const float*)d_in[1];   // (32, 2048)
    const float* shg   = (const float*)d_in[2];   // (32, 1, 1024, 1024)
    float* out = (float*)d_out;

    k_init<<<1, 1024>>>();
    k_hilbert<<<8, 128>>>(pred);
    k_shg<<<8192, 128>>>(shg);
    k_final<<<1, 1024>>>(label, out);
}

// round 2
// speedup vs baseline: 1.6218x; 1.6218x over previous
#include <cuda_runtime.h>
#include <cstdint>
#include <cstddef>

#define NN 1024
#define BB 32

// ---------------- device scratch (no allocations allowed) ----------------
static __device__ float2   g_tw[NN];        // W1024^{lane*brev5(j)} table
static __device__ float2   g_pa[BB * NN];   // analytic signal
static __device__ float2   g_bb[BB * NN];   // pa * SHIFT_FACTOR
static __device__ double   g_Sp[BB];        // sum of unnormalized shg
static __device__ double   g_Spt[BB];       // sum shg * tref
static __device__ double   g_St[BB];        // sum tref
static __device__ double   g_Stt[BB];       // sum tref^2
static __device__ unsigned g_M[BB];         // max shg (float bits)

__device__ __forceinline__ int br5(int j) {
    return (int)(__brev((unsigned)j) >> 27);
}

// ---------------- fully unrolled radix-2 DIF FFT-32 in registers ----------
// input natural order, output bit-reversed: out[j] = X[brev5(j)]
__device__ __forceinline__ void fft32(float* ar, float* ai) {
    const float W32r[16] = {
        1.00000000f, 0.98078528f, 0.92387953f, 0.83146961f,
        0.70710678f, 0.55557023f, 0.38268343f, 0.19509032f,
        0.00000000f,-0.19509032f,-0.38268343f,-0.55557023f,
       -0.70710678f,-0.83146961f,-0.92387953f,-0.98078528f };
    const float W32i[16] = {
        0.00000000f,-0.19509032f,-0.38268343f,-0.55557023f,
       -0.70710678f,-0.83146961f,-0.92387953f,-0.98078528f,
       -1.00000000f,-0.98078528f,-0.92387953f,-0.83146961f,
       -0.70710678f,-0.55557023f,-0.38268343f,-0.19509032f };
    #pragma unroll
    for (int st = 0; st < 5; st++) {
        const int h = 16 >> st;
        const int tstep = 1 << st;
        #pragma unroll
        for (int s = 0; s < 32; s += 2 * h) {
            #pragma unroll
            for (int j = 0; j < h; j++) {
                const int i0 = s + j, i1 = i0 + h;
                float ur = ar[i0], ui = ai[i0];
                float vr = ar[i1], vi = ai[i1];
                ar[i0] = ur + vr; ai[i0] = ui + vi;
                float dr = ur - vr, di = ui - vi;
                const int w = j * tstep;
                if (w == 0)      { ar[i1] = dr;  ai[i1] = di;  }
                else if (w == 8) { ar[i1] = di;  ai[i1] = -dr; }   // *(0,-1)
                else {
                    float wr = W32r[w], wi = W32i[w];
                    ar[i1] = dr * wr - di * wi;
                    ai[i1] = di * wr + dr * wi;
                }
            }
        }
    }
}

// FFT-1024: lane t holds x[t + 32*q] in reg q. Output: reg j of lane l holds
// X[l + 32*brev5(j)]. One padded 33x32 smem buffer reused for re and im.
__device__ __forceinline__ void fft1024(float* xr, float* xi,
                                        float* sm, int lane) {
    fft32(xr, xi);                 // per-lane DFT over q
    #pragma unroll
    for (int j = 0; j < 32; j++) { // twiddle W1024^{lane * brev5(j)}
        float2 w = g_tw[j * 32 + lane];
        float r = xr[j] * w.x - xi[j] * w.y;
        xi[j]   = xi[j] * w.x + xr[j] * w.y;
        xr[j]   = r;
    }
    __syncwarp();
    #pragma unroll
    for (int j = 0; j < 32; j++) sm[br5(j) * 33 + lane] = xr[j];
    __syncwarp();
    #pragma unroll
    for (int r = 0; r < 32; r++) xr[r] = sm[lane * 33 + r];
    __syncwarp();
    #pragma unroll
    for (int j = 0; j < 32; j++) sm[br5(j) * 33 + lane] = xi[j];
    __syncwarp();
    #pragma unroll
    for (int r = 0; r < 32; r++) xi[r] = sm[lane * 33 + r];
    __syncwarp();
    fft32(xr, xi);                 // DFT over former lane index
}

// ---------------- K0: twiddle table + accumulator/output reset ------------
__global__ void k_init(float* __restrict__ out) {
    int tid = threadIdx.x;
    int j = tid >> 5, t = tid & 31;
    int e = (t * br5(j)) & 1023;
    float s, c;
    sincospif(-(float)e * (1.0f / 512.0f), &s, &c);
    g_tw[tid] = make_float2(c, s);
    if (tid < BB) {
        g_Sp[tid] = 0.0; g_Spt[tid] = 0.0;
        g_St[tid] = 0.0; g_Stt[tid] = 0.0;
        g_M[tid] = 0u;
    }
    if (tid == 0) out[0] = 0.f;
}

// ---------------- K1: Hilbert (analytic signal) + SHIFT_FACTOR fold -------
__global__ void __launch_bounds__(128) k_hilbert(const float* __restrict__ pred) {
    __shared__ float sm[4][33 * 32];
    int warp = threadIdx.x >> 5, lane = threadIdx.x & 31;
    int b = blockIdx.x * 4 + warp;

    float xr[32], xi[32];
    const float* p = pred + b * NN;
    #pragma unroll
    for (int q = 0; q < 32; q++) { xr[q] = p[lane + 32 * q]; xi[q] = 0.f; }

    fft1024(xr, xi, sm[warp], lane);

    // mask (0 for k<512, 1 at 512, 2 for k>512), conj for inverse transform
    float yr[32], yi[32];
    #pragma unroll
    for (int p2 = 0; p2 < 32; p2++) {
        int j = br5(p2);                 // source reg with freq lane + 32*p2
        int k = lane + 32 * p2;
        float f = (k > 512) ? 2.f : ((k == 512) ? 1.f : 0.f);
        yr[p2] =  xr[j] * f;
        yi[p2] = -xi[j] * f;
    }
    fft1024(yr, yi, sm[warp], lane);  // ifft via conj trick

    const float phi = (float)(2.0 * 1.175e15 * 1.5e-15);  // 2*W_CENTER*DELTA_TAU
    #pragma unroll
    for (int j = 0; j < 32; j++) {
        int m = lane + 32 * br5(j);
        float prr =  yr[j] * (1.f / 1024.f);
        float pii = -yi[j] * (1.f / 1024.f);
        g_pa[b * NN + m] = make_float2(prr, pii);
        float argf = phi * (float)(m - 512);
        float si, cr;
        sincosf(argf, &si, &cr);                 // SF = cr - i*si
        g_bb[b * NN + m] = make_float2(prr * cr + pii * si,
                                       pii * cr - prr * si);
    }
}

// ---------------- K2: SHG rows — FFT + streaming reduction ----------------
__global__ void __launch_bounds__(128) k_shg(const float* __restrict__ tref) {
    __shared__ float sm[4][33 * 32];
    __shared__ float s_acc[4][4];
    __shared__ float s_mx[4];
    int warp = threadIdx.x >> 5, lane = threadIdx.x & 31;
    int w = blockIdx.x * 4 + warp;
    int b = w >> 10;          // 1024 rows per batch; whole CTA shares b
    int d = w & 1023;

    const float2* pb = g_bb + b * NN;
    const float2* pa = g_pa + b * NN;
    float xr[32], xi[32];
    #pragma unroll
    for (int q = 0; q < 32; q++) {
        int n = lane + 32 * q;
        float2 bv = pb[n];
        float2 av = pa[(n - d + 512) & 1023];
        xr[q] = bv.x * av.x - bv.y * av.y;
        xi[q] = bv.x * av.y + bv.y * av.x;
    }

    fft1024(xr, xi, sm[warp], lane);

    const float* trow = tref + (size_t)(b * 1024 + d) * 1024;
    float sp = 0.f, spt = 0.f, st = 0.f, stt = 0.f, mx = 0.f;
    #pragma unroll
    for (int j = 0; j < 32; j++) {
        float m = xr[j] * xr[j] + xi[j] * xi[j];
        int col = (lane + 32 * br5(j) + 512) & 1023;  // output fftshift remap
        float tv = __ldcs(trow + col);
        sp += m; spt += m * tv; st += tv; stt += tv * tv;
        mx = fmaxf(mx, m);
    }
    #pragma unroll
    for (int o = 16; o; o >>= 1) {
        sp  += __shfl_xor_sync(0xffffffffu, sp, o);
        spt += __shfl_xor_sync(0xffffffffu, spt, o);
        st  += __shfl_xor_sync(0xffffffffu, st, o);
        stt += __shfl_xor_sync(0xffffffffu, stt, o);
        mx = fmaxf(mx, __shfl_xor_sync(0xffffffffu, mx, o));
    }
    if (lane == 0) {
        s_acc[warp][0] = sp; s_acc[warp][1] = spt;
        s_acc[warp][2] = st; s_acc[warp][3] = stt;
        s_mx[warp] = mx;
    }
    __syncthreads();
    if (threadIdx.x == 0) {
        double a0 = 0, a1 = 0, a2 = 0, a3 = 0; float mm = 0.f;
        #pragma unroll
        for (int i2 = 0; i2 < 4; i2++) {
            a0 += (double)s_acc[i2][0]; a1 += (double)s_acc[i2][1];
            a2 += (double)s_acc[i2][2]; a3 += (double)s_acc[i2][3];
            mm = fmaxf(mm, s_mx[i2]);
        }
        atomicAdd(&g_Sp[b],  a0);
        atomicAdd(&g_Spt[b], a1);
        atomicAdd(&g_St[b],  a2);
        atomicAdd(&g_Stt[b], a3);
        atomicMax(&g_M[b], __float_as_uint(mm));
    }
}

// ---------------- K3: per-batch MSE + FROG, atomic mean -------------------
__global__ void __launch_bounds__(256) k_loss(const float* __restrict__ label,
                                              float* __restrict__ out) {
    __shared__ int   s_f[8], s_l[8];
    __shared__ float s_s[8];
    int b = blockIdx.x;
    int tid = threadIdx.x, lane = tid & 31, warp = tid >> 5;
    const float* lab = label + b * 2 * NN;

    // pass 1: first/last index of |component| > threshold
    int fst = NN, lst = -1;
    #pragma unroll
    for (int q = 0; q < 4; q++) {
        int t = tid + 256 * q;
        float lr = lab[t], li = lab[NN + t];
        if (fabsf(lr) > 0.01f) { fst = min(fst, t); lst = max(lst, t); }
        if (fabsf(li) > 0.01f) { fst = min(fst, t); lst = max(lst, t); }
    }
    #pragma unroll
    for (int o = 16; o; o >>= 1) {
        fst = min(fst, __shfl_xor_sync(0xffffffffu, fst, o));
        lst = max(lst, __shfl_xor_sync(0xffffffffu, lst, o));
    }
    if (lane == 0) { s_f[warp] = fst; s_l[warp] = lst; }
    __syncthreads();
    int first = NN, last = -1;
    #pragma unroll
    for (int i = 0; i < 8; i++) { first = min(first, s_f[i]); last = max(last, s_l[i]); }
    // reference semantics: a component with no hits contributes first=0,last=N-1
    // Careful: reference computes first/last per component, then min/max.
    // If NEITHER component has hits anywhere, first=0,last=N-1. If one has
    // hits, the empty one still contributes (0, N-1) -> first=0, last=N-1.
    // Reproduce exactly:
    {
        __shared__ int s_hr[8], s_hi[8], s_fr[8], s_lr2[8], s_fi[8], s_li2[8];
        int fr = NN, lr2 = -1, fi = NN, li2 = -1;
        #pragma unroll
        for (int q = 0; q < 4; q++) {
            int t = tid + 256 * q;
            float lr = lab[t], li = lab[NN + t];
            if (fabsf(lr) > 0.01f) { fr = min(fr, t); lr2 = max(lr2, t); }
            if (fabsf(li) > 0.01f) { fi = min(fi, t); li2 = max(li2, t); }
        }
        #pragma unroll
        for (int o = 16; o; o >>= 1) {
            fr  = min(fr,  __shfl_xor_sync(0xffffffffu, fr, o));
            lr2 = max(lr2, __shfl_xor_sync(0xffffffffu, lr2, o));
            fi  = min(fi,  __shfl_xor_sync(0xffffffffu, fi, o));
            li2 = max(li2, __shfl_xor_sync(0xffffffffu, li2, o));
        }
        if (lane == 0) { s_fr[warp]=fr; s_lr2[warp]=lr2; s_fi[warp]=fi; s_li2[warp]=li2;
                         s_hr[warp]=0; s_hi[warp]=0; }
        __syncthreads();
        int FR = NN, LR = -1, FI = NN, LI = -1;
        #pragma unroll
        for (int i = 0; i < 8; i++) {
            FR = min(FR, s_fr[i]); LR = max(LR, s_lr2[i]);
            FI = min(FI, s_fi[i]); LI = max(LI, s_li2[i]);
        }
        if (FR == NN) FR = 0;
        if (FI == NN) FI = 0;
        if (LR < 0)   LR = NN - 1;
        if (LI < 0)   LI = NN - 1;
        first = min(FR, FI);
        last  = max(LR, LI);
    }

    // pass 2: masked MSE terms
    float s = 0.f;
    #pragma unroll
    for (int q = 0; q < 4; q++) {
        int t = tid + 256 * q;
        float2 pav = g_pa[b * NN + t];
        float pr = pav.x, pi = pav.y;
        float lr = lab[t], li = lab[NN + t];
        bool inr = (t >= first) && (t < last);
        float pm = inr ? 10.f : 1.f;
        float d1 = pr - lr, d2 = pi - li;
        float d3 = (pr * pr + pi * pi) - (lr * lr + li * li);
        float dph = atan2f(pi, pr) - atan2f(li, lr);
        s += (d1 * d1 + d2 * d2 + d3 * d3) * pm + (inr ? dph * dph : 0.f);
    }
    #pragma unroll
    for (int o = 16; o; o >>= 1) s += __shfl_xor_sync(0xffffffffu, s, o);
    if (lane == 0) s_s[warp] = s;
    __syncthreads();
    if (tid == 0) {
        float ss = 0.f;
        #pragma unroll
        for (int i = 0; i < 8; i++) ss += s_s[i];
        float mse = ss * (1.f / (4.f * 1024.f));   // /N and /MSE_WSUM
        double M   = (double)__uint_as_float(g_M[b]);
        double mu  = (g_Spt[b] / M) / g_Stt[b];
        double dif = g_Sp[b] / M - mu * g_St[b];
        float frog = (float)(fabs(dif) * (1.0 / 1024.0));  // sqrt(r/N^2)
        atomicAdd(out, (mse + frog) * (1.f / 32.f));
    }
}

// ---------------- launch ---------------------------------------------------
extern "C" void kernel_launch(void* const* d_in, const int* in_sizes, int n_in,
                              void* d_out, int out_size) {
    (void)in_sizes; (void)n_in; (void)out_size;
    const float* pred  = (const float*)d_in[0];   // (32, 1024)
    const float* label = (const float*)d_in[1];   // (32, 2048)
    const float* shg   = (const float*)d_in[2];   // (32, 1, 1024, 1024)
    float* out = (float*)d_out;

    k_init<<<1, 1024>>>(out);
    k_hilbert<<<8, 128>>>(pred);
    k_shg<<<8192, 128>>>(shg);
    k_loss<<<32, 256>>>(label, out);
}